// round 3
// baseline (speedup 1.0000x reference)
#include <cuda_runtime.h>

// RoiPooling: fmap [1,128,128,256] f32 NHWC, roi_edges [R,4] f32
// out [R,7,7,256] f32. Adaptive max pool per ROI, bins per reference
// _bin_size / min(idx//m, 6) semantics.

#define H_DIM 128
#define W_DIM 128
#define C_VEC 64          // 256 channels / 4 (float4)
#define OUT_H 7
#define OUT_W 7

__device__ __forceinline__ int bin_size(int L) {
    int xup = (L + OUT_H - 1) / OUT_H;            // ceil(L/7)
    int m = (xup * (OUT_H - 1) >= L) ? (xup - 1) : xup;
    return m > 1 ? m : 1;
}

__global__ __launch_bounds__(C_VEC, 16)
void roi_pool_kernel(const float4* __restrict__ fmap,   // [128,128,64] float4
                     const float4* __restrict__ rois,   // [R] float4 (l,r,t,b normalized)
                     float4* __restrict__ out)          // [R,7,7,64] float4
{
    const int r   = blockIdx.x;   // ROI index
    const int i   = blockIdx.y;   // output row 0..6
    const int tid = threadIdx.x;  // 0..63 channel-group

    const float4 e = rois[r];
    const int l  = __float2int_rn(128.0f * e.x);
    const int rr = __float2int_rn(128.0f * e.y);
    const int t  = __float2int_rn(128.0f * e.z);
    const int b  = __float2int_rn(128.0f * e.w);

    int Lh = b - t; Lh = Lh < OUT_H ? OUT_H : (Lh > 32 ? 32 : Lh);
    int Lw = rr - l; Lw = Lw < OUT_W ? OUT_W : (Lw > 32 ? 32 : Lw);

    const int mh = bin_size(Lh);
    const int mw = bin_size(Lw);

    // Row range for this output row i (bin 6 absorbs the tail).
    int y0 = i * mh;
    int y1 = (i == OUT_H - 1) ? Lh : ((i + 1) * mh);
    if (y1 > Lh) y1 = Lh;

    // Column bin edges, fully unrolled so they stay in registers.
    int x0a[OUT_W], x1a[OUT_W];
#pragma unroll
    for (int j = 0; j < OUT_W; ++j) {
        x0a[j] = j * mw;
        int xe = (j == OUT_W - 1) ? Lw : ((j + 1) * mw);
        x1a[j] = xe > Lw ? Lw : xe;
    }

    const float NEG = __int_as_float(0xff800000);   // -inf
    float4 acc[OUT_W];
#pragma unroll
    for (int j = 0; j < OUT_W; ++j)
        acc[j] = make_float4(NEG, NEG, NEG, NEG);

    // Scan the bin-row region. 7 independent accumulator chains per y
    // give enough MLP to hide L2 latency.
    for (int y = y0; y < y1; ++y) {
        const float4* row = fmap + ((size_t)(t + y) * W_DIM + l) * C_VEC + tid;
#pragma unroll
        for (int j = 0; j < OUT_W; ++j) {
            const int xe = x1a[j];
#pragma unroll 4
            for (int x = x0a[j]; x < xe; ++x) {
                float4 v = row[(size_t)x * C_VEC];
                acc[j].x = fmaxf(acc[j].x, v.x);
                acc[j].y = fmaxf(acc[j].y, v.y);
                acc[j].z = fmaxf(acc[j].z, v.z);
                acc[j].w = fmaxf(acc[j].w, v.w);
            }
        }
    }

    float4* obase = out + ((size_t)r * OUT_H + i) * OUT_W * C_VEC + tid;
#pragma unroll
    for (int j = 0; j < OUT_W; ++j)
        obase[(size_t)j * C_VEC] = acc[j];
}

extern "C" void kernel_launch(void* const* d_in, const int* in_sizes, int n_in,
                              void* d_out, int out_size)
{
    const float4* fmap = (const float4*)d_in[0];   // [1,128,128,256] f32
    const float4* rois = (const float4*)d_in[1];   // [R,4] f32
    float4* out = (float4*)d_out;

    const int R = in_sizes[1] / 4;

    dim3 grid(R, OUT_H);
    dim3 block(C_VEC);
    roi_pool_kernel<<<grid, block>>>(fmap, rois, out);
}

// round 4
// speedup vs baseline: 1.4815x; 1.4815x over previous
#include <cuda_runtime.h>

// RoiPooling: fmap [1,128,128,256] f32 NHWC, roi_edges [R,4] f32
// out [R,7,7,256] f32. Adaptive max pool, reference _bin_size semantics.

#define H_DIM 128
#define W_DIM 128
#define C_VEC 64          // 256 channels / 4 (float4)
#define OUT_H 7
#define OUT_W 7
#define ROW_STRIDE (W_DIM * C_VEC)   // float4 elements per fmap row

__device__ __forceinline__ int bin_size(int L) {
    int xup = (L + OUT_H - 1) / OUT_H;            // ceil(L/7)
    int m = (xup * (OUT_H - 1) >= L) ? (xup - 1) : xup;
    return m > 1 ? m : 1;
}

__device__ __forceinline__ void fold(float4& a, const float4& v) {
    a.x = fmaxf(a.x, v.x);
    a.y = fmaxf(a.y, v.y);
    a.z = fmaxf(a.z, v.z);
    a.w = fmaxf(a.w, v.w);
}

// Scan rows y = ty, ty+2, ... < cnt for one out-row. Bins 0..5 have
// compile-time width MW (immediate-offset, branch-free loads); bin 6 has
// dynamic width wl in [1,6], handled by index-clamping (max is idempotent,
// duplicate loads hit L1 on a just-fetched line).
template<int MW>
__device__ __forceinline__ void scan_rows(const float4* __restrict__ fp,
                                          int cnt, int ty, int wl,
                                          float4 acc[OUT_W])
{
    for (int y = ty; y < cnt; y += 2) {
        const float4* row = fp + (size_t)y * ROW_STRIDE;
#pragma unroll
        for (int j = 0; j < OUT_W - 1; ++j) {
#pragma unroll
            for (int k = 0; k < MW; ++k) {
                float4 v = __ldg(row + (j * MW + k) * C_VEC);
                fold(acc[j], v);
            }
        }
        const float4* rowt = row + (OUT_W - 1) * MW * C_VEC;
        int wlm1 = wl - 1;
#pragma unroll
        for (int k = 0; k < 6; ++k) {
            int kk = k < wl ? k : wlm1;
            float4 v = __ldg(rowt + kk * C_VEC);
            fold(acc[OUT_W - 1], v);
        }
    }
}

__global__ __launch_bounds__(128, 6)
void roi_pool_kernel(const float4* __restrict__ fmap,   // [128,128,64] float4
                     const float4* __restrict__ rois,   // [R] (l,r,t,b)
                     float4* __restrict__ out)          // [R,7,7,64] float4
{
    const int r   = blockIdx.x;       // ROI index
    const int i   = blockIdx.y;       // output row 0..6
    const int tid = threadIdx.x;      // 0..63 channel-group
    const int ty  = threadIdx.y;      // 0..1 row-slice

    const float4 e = rois[r];
    const int l  = __float2int_rn(128.0f * e.x);
    const int rr = __float2int_rn(128.0f * e.y);
    const int t  = __float2int_rn(128.0f * e.z);
    const int b  = __float2int_rn(128.0f * e.w);

    int Lh = b - t; Lh = Lh < OUT_H ? OUT_H : (Lh > 32 ? 32 : Lh);
    int Lw = rr - l; Lw = Lw < OUT_W ? OUT_W : (Lw > 32 ? 32 : Lw);

    const int mh = bin_size(Lh);
    const int mw = bin_size(Lw);
    const int wl = Lw - (OUT_W - 1) * mw;          // last-bin width, 1..6

    const int y0 = i * mh;
    int y1 = (i == OUT_H - 1) ? Lh : (i + 1) * mh;
    if (y1 > Lh) y1 = Lh;
    const int cnt = y1 - y0;                       // 1..6

    const float NEG = __int_as_float(0xff800000);  // -inf
    float4 acc[OUT_W];
#pragma unroll
    for (int j = 0; j < OUT_W; ++j)
        acc[j] = make_float4(NEG, NEG, NEG, NEG);

    const float4* fp = fmap + ((size_t)(t + y0) * W_DIM + l) * C_VEC + tid;

    switch (mw) {
        case 1: scan_rows<1>(fp, cnt, ty, wl, acc); break;
        case 2: scan_rows<2>(fp, cnt, ty, wl, acc); break;
        case 3: scan_rows<3>(fp, cnt, ty, wl, acc); break;
        case 4: scan_rows<4>(fp, cnt, ty, wl, acc); break;
        default: scan_rows<5>(fp, cnt, ty, wl, acc); break;
    }

    // Combine the two row-slices via smem, then ty==0 stores.
    __shared__ float4 part[OUT_W][C_VEC];
    if (ty == 1) {
#pragma unroll
        for (int j = 0; j < OUT_W; ++j)
            part[j][tid] = acc[j];
    }
    __syncthreads();
    if (ty == 0) {
        float4* obase = out + ((size_t)r * OUT_H + i) * OUT_W * C_VEC + tid;
#pragma unroll
        for (int j = 0; j < OUT_W; ++j) {
            fold(acc[j], part[j][tid]);
            obase[(size_t)j * C_VEC] = acc[j];
        }
    }
}

extern "C" void kernel_launch(void* const* d_in, const int* in_sizes, int n_in,
                              void* d_out, int out_size)
{
    const float4* fmap = (const float4*)d_in[0];   // [1,128,128,256] f32
    const float4* rois = (const float4*)d_in[1];   // [R,4] f32
    float4* out = (float4*)d_out;

    const int R = in_sizes[1] / 4;

    dim3 grid(R, OUT_H);
    dim3 block(C_VEC, 2);
    roi_pool_kernel<<<grid, block>>>(fmap, rois, out);
}